// round 16
// baseline (speedup 1.0000x reference)
#include <cuda_runtime.h>
#include <math.h>

// SDF2: mesh -> voxel (inside ? distance : 0) grid. Round-16:
//   - round-15 ortho-frame body (WIN: 75.8us, rel_err 5e-6) with one change:
//     all 7 affine states evaluated per-k as  state = fmaf((float)k, step, base)
//     -> FFMA with immediate multiplier (rt_SMSP=1, vs FADD rt=2), and the
//     loop-carried FADD chains disappear (k is a compile-time constant in the
//     unrolled loop). fma-pipe load per k: 34 -> 27 SMSP-cyc; issue (28)
//     becomes the binding constraint.
//   - init kernel vectorized (uint4 stores).
//   Skeleton: KPT=32, 74 balanced chunks (592 blocks = 148x4), hoisted parity,
//   RED-atomic reduce (atomicMin float bits), trivial finalize.

#define G_DIM    32
#define N_PTS    (G_DIM * G_DIM * G_DIM)          // 32768
#define N_FACES  2048
#define N_CHUNKS 74
#define TRI_MAX  28
#define KPT      32
#define N_GROUPS (N_PTS / KPT)                    // 1024
#define THREADS  128
#define EPSF     1e-12f
#define INF_F    __int_as_float(0x7F800000)

__device__ unsigned g_md2min[N_PTS];              // float bits, monotone (md2>=0)
__device__ unsigned g_parity[N_GROUPS];           // 32 parity bits per word

__global__ void __launch_bounds__(256)
sdf_init()
{
    int i = blockIdx.x * 256 + threadIdx.x;       // [0, 8192) covers N_PTS/4
    uint4 inf4 = make_uint4(0x7F800000u, 0x7F800000u, 0x7F800000u, 0x7F800000u);
    reinterpret_cast<uint4*>(g_md2min)[i] = inf4;
    if (i < N_GROUPS) g_parity[i] = 0u;
}

// interval of k where L0 + k*i > 0 (strict); inv_i = 1/i (inf ok when i==0)
__device__ __forceinline__ void lin_interval(float L0, float i, float inv_i,
                                             float& lo, float& hi)
{
    float kl = -L0 * inv_i;
    if (i > 0.0f)      { lo = kl;     hi = INF_F; }
    else if (i < 0.0f) { lo = -INF_F; hi = kl; }
    else               { lo = (L0 > 0.0f) ? -INF_F : INF_F;
                         hi = (L0 > 0.0f) ?  INF_F : -INF_F; }
}

__global__ void __launch_bounds__(THREADS, 4)
sdf_main(const int* __restrict__ faces, const float* __restrict__ verts)
{
    // 12 float4 per triangle:
    // 0: ê1.xyz, L1   1: ê2.xyz, L2   2: ê3.xyz, L3      (edges AB, BC, CA)
    // 3: m1.xyz, is1  4: m2.xyz, is2  5: m3.xyz, is3
    // 6: ŵ.xyz, ipw   7: A.xyz, nz    8: B.xyz, nondeg   9: C.xyz, 0
    // 10: iq1, iq2, iq3, 0            11: inv_is1, inv_is2, inv_is3, 0
    __shared__ float4 tc[12 * TRI_MAX];           // 5.4 KB

    const int start = (blockIdx.y * N_FACES) / N_CHUNKS;
    const int end   = ((blockIdx.y + 1) * N_FACES) / N_CHUNKS;
    const int ntri  = end - start;
    const float dz  = 1.0f / (float)G_DIM;

    if (threadIdx.x < ntri) {
        const int f = threadIdx.x;
        const int base = (start + f) * 3;
        const float* va  = verts + 3 * faces[base + 0];
        const float* vbv = verts + 3 * faces[base + 1];
        const float* vcv = verts + 3 * faces[base + 2];
        float Ax = va[0],  Ay = va[1],  Az = va[2];
        float Bx = vbv[0], By = vbv[1], Bz = vbv[2];
        float Cx = vcv[0], Cy = vcv[1], Cz = vcv[2];

        // cyclic edges: E1 = A->B, E2 = B->C, E3 = C->A
        float e1x = Bx-Ax, e1y = By-Ay, e1z = Bz-Az;
        float e2x = Cx-Bx, e2y = Cy-By, e2z = Cz-Bz;
        float e3x = Ax-Cx, e3y = Ay-Cy, e3z = Az-Cz;
        float L1 = sqrtf(e1x*e1x + e1y*e1y + e1z*e1z);
        float L2 = sqrtf(e2x*e2x + e2y*e2y + e2z*e2z);
        float L3 = sqrtf(e3x*e3x + e3y*e3y + e3z*e3z);

        float acx = Cx-Ax, acy = Cy-Ay, acz = Cz-Az;
        float nx = e1y*acz - e1z*acy;
        float ny = e1z*acx - e1x*acz;
        float nz = e1x*acy - e1y*acx;
        float gram = nx*nx + ny*ny + nz*nz;
        bool nondeg = gram > 1e-12f;

        float wx, wy, wz;
        if (nondeg) {
            float inv_n = rsqrtf(gram);
            wx = nx*inv_n; wy = ny*inv_n; wz = nz*inv_n;
        } else {
            float bx2 = 1.0f, by2 = 0.0f, bz2 = 0.0f;
            if      (L1 > 0.0f) { float r = 1.0f/L1; bx2 = e1x*r; by2 = e1y*r; bz2 = e1z*r; }
            else if (L2 > 0.0f) { float r = 1.0f/L2; bx2 = e2x*r; by2 = e2y*r; bz2 = e2z*r; }
            else if (L3 > 0.0f) { float r = 1.0f/L3; bx2 = e3x*r; by2 = e3y*r; bz2 = e3z*r; }
            float px_ = (fabsf(bx2) < 0.9f) ? 1.0f : 0.0f;
            float py_ = 1.0f - px_;
            float cx2 = by2*0.0f - bz2*py_;
            float cy2 = bz2*px_ - bx2*0.0f;
            float cz2 = bx2*py_ - by2*px_;
            float rn = rsqrtf(fmaxf(cx2*cx2 + cy2*cy2 + cz2*cz2, EPSF));
            wx = cx2*rn; wy = cy2*rn; wz = cz2*rn;
        }
        // u0: arbitrary unit perpendicular to w (for zero-length edges)
        float u0x, u0y, u0z;
        {
            float px_ = (fabsf(wx) < 0.9f) ? 1.0f : 0.0f;
            float py_ = 1.0f - px_;
            float cx2 = wy*0.0f - wz*py_;
            float cy2 = wz*px_ - wx*0.0f;
            float cz2 = wx*py_ - wy*px_;
            float rn = rsqrtf(fmaxf(cx2*cx2 + cy2*cy2 + cz2*cz2, EPSF));
            u0x = cx2*rn; u0y = cy2*rn; u0z = cz2*rn;
        }

        float h1x, h1y, h1z, h2x, h2y, h2z, h3x, h3y, h3z;
        if (L1 > 0.0f) { float r = 1.0f/L1; h1x = e1x*r; h1y = e1y*r; h1z = e1z*r; }
        else           { h1x = u0x; h1y = u0y; h1z = u0z; }
        if (L2 > 0.0f) { float r = 1.0f/L2; h2x = e2x*r; h2y = e2y*r; h2z = e2z*r; }
        else           { h2x = u0x; h2y = u0y; h2z = u0z; }
        if (L3 > 0.0f) { float r = 1.0f/L3; h3x = e3x*r; h3y = e3y*r; h3z = e3z*r; }
        else           { h3x = u0x; h3y = u0y; h3z = u0z; }

        // m_i = w x ê_i, flipped so the opposite vertex has s > 0
        float m1x = wy*h1z - wz*h1y, m1y = wz*h1x - wx*h1z, m1z = wx*h1y - wy*h1x;
        float m2x = wy*h2z - wz*h2y, m2y = wz*h2x - wx*h2z, m2z = wx*h2y - wy*h2x;
        float m3x = wy*h3z - wz*h3y, m3y = wz*h3x - wx*h3z, m3z = wx*h3y - wy*h3x;
        float sC = (Cx-Ax)*m1x + (Cy-Ay)*m1y + (Cz-Az)*m1z;
        if (sC < 0.0f) { m1x = -m1x; m1y = -m1y; m1z = -m1z; }
        float sA = (Ax-Bx)*m2x + (Ay-By)*m2y + (Az-Bz)*m2z;
        if (sA < 0.0f) { m2x = -m2x; m2y = -m2y; m2z = -m2z; }
        float sB = (Bx-Cx)*m3x + (By-Cy)*m3y + (Bz-Cz)*m3z;
        if (sB < 0.0f) { m3x = -m3x; m3y = -m3y; m3z = -m3z; }

        float is1 = m1z*dz, is2 = m2z*dz, is3 = m3z*dz;

        tc[12*f + 0]  = make_float4(h1x, h1y, h1z, L1);
        tc[12*f + 1]  = make_float4(h2x, h2y, h2z, L2);
        tc[12*f + 2]  = make_float4(h3x, h3y, h3z, L3);
        tc[12*f + 3]  = make_float4(m1x, m1y, m1z, is1);
        tc[12*f + 4]  = make_float4(m2x, m2y, m2z, is2);
        tc[12*f + 5]  = make_float4(m3x, m3y, m3z, is3);
        tc[12*f + 6]  = make_float4(wx, wy, wz, wz*dz);
        tc[12*f + 7]  = make_float4(Ax, Ay, Az, nz);
        tc[12*f + 8]  = make_float4(Bx, By, Bz, nondeg ? 1.0f : 0.0f);
        tc[12*f + 9]  = make_float4(Cx, Cy, Cz, 0.0f);
        tc[12*f + 10] = make_float4(h1z*dz, h2z*dz, h3z*dz, 0.0f);
        tc[12*f + 11] = make_float4(1.0f/is1, 1.0f/is2, 1.0f/is3, 0.0f);
    }
    __syncthreads();

    const int g  = blockIdx.x * THREADS + threadIdx.x;    // [0, 1024)
    const int ix = g >> 5;
    const int iy = g & 31;

    const float px  = ((float)ix + 0.5f) * dz;
    const float py  = ((float)iy + 0.5f) * dz;
    const float pz0 = 0.5f * dz;
    const int pbase = (ix * 32 + iy) * 32;

    float md[KPT];
    #pragma unroll
    for (int k = 0; k < KPT; ++k) md[k] = INF_F;
    unsigned par = 0u;

    for (int f = 0; f < ntri; ++f) {
        const float4 c0  = tc[12*f + 0];
        const float4 c1  = tc[12*f + 1];
        const float4 c2  = tc[12*f + 2];
        const float4 c3  = tc[12*f + 3];
        const float4 c4  = tc[12*f + 4];
        const float4 c5  = tc[12*f + 5];
        const float4 c6  = tc[12*f + 6];
        const float4 c7  = tc[12*f + 7];
        const float4 c8  = tc[12*f + 8];
        const float4 c9  = tc[12*f + 9];
        const float4 c10 = tc[12*f + 10];
        const float4 c11 = tc[12*f + 11];
        const float L1 = c0.w, L2 = c1.w, L3 = c2.w;

        // ---- ray crossing (den == nz), fully hoisted ----
        {
            float cpx2 = px - c9.x, cpy2 = py - c9.y;
            float nz = c7.w;
            float e0 = c8.y - c9.y;                       // By - Cy
            float e1 = c9.x - c8.x;                       // Cx - Bx
            float un = e0 * cpx2 + e1 * cpy2;
            float vn = (c9.y - c7.y) * cpx2 + (c7.x - c9.x) * cpy2;
            float wn = nz - un - vn;
            bool c2d = (fabsf(nz) >= EPSF)
                     & (un * nz >= 0.0f) & (vn * nz >= 0.0f) & (wn * nz >= 0.0f);
            if (c2d) {
                float zhit = __fdividef(un * c7.z + vn * c8.z + wn * c9.z, nz);
                float fcnt = (zhit - pz0) * (float)G_DIM;
                int n = (int)ceilf(fminf(fmaxf(fcnt, 0.0f), (float)KPT));
                par ^= (n >= 32) ? 0xFFFFFFFFu : ((1u << n) - 1u);
            }
        }

        // ---- per-pair frame-coordinate init (7 dots) ----
        const float apx = px - c7.x, apy = py - c7.y; const float apz = pz0 - c7.z;
        const float bpx = px - c8.x, bpy = py - c8.y; const float bpz = pz0 - c8.z;
        const float cpx = px - c9.x, cpy = py - c9.y; const float cpz = pz0 - c9.z;
        const float q1 = apx*c0.x + apy*c0.y + apz*c0.z;
        const float s1 = apx*c3.x + apy*c3.y + apz*c3.z;
        const float q2 = bpx*c1.x + bpy*c1.y + bpz*c1.z;
        const float s2 = bpx*c4.x + bpy*c4.y + bpz*c4.z;
        const float q3 = cpx*c2.x + cpy*c2.y + cpz*c2.z;
        const float s3 = cpx*c5.x + cpy*c5.y + cpz*c5.z;
        const float pw = apx*c6.x + apy*c6.y + apz*c6.z;
        const float iq1 = c10.x, iq2 = c10.y, iq3 = c10.z;
        const float is1 = c3.w,  is2 = c4.w,  is3 = c5.w, ipw = c6.w;

        // inside interval (all s_e > 0), gated off for degenerate faces
        unsigned imask = 0u;
        if (c8.w != 0.0f) {
            float lo1, hi1, lo2, hi2, lo3, hi3;
            lin_interval(s1, is1, c11.x, lo1, hi1);
            lin_interval(s2, is2, c11.y, lo2, hi2);
            lin_interval(s3, is3, c11.z, lo3, hi3);
            float lo = fmaxf(fmaxf(lo1, lo2), lo3);
            float hi = fminf(fminf(hi1, hi2), hi3);
            int ilo = (int)ceilf(fminf(fmaxf(lo, 0.0f), 33.0f));
            int ihi = (int)ceilf(fminf(fmaxf(hi, 0.0f), 32.0f));
            unsigned long long below_hi = (1ull << ihi) - 1ull;
            unsigned long long below_lo = (1ull << ilo) - 1ull;
            imask = (unsigned)(below_hi & ~below_lo);
        }

        #pragma unroll
        for (int k = 0; k < KPT; ++k) {
            // FFMA-imm (rt=1) state evaluation: k is a compile-time float
            const float fk = (float)k;
            float q1k = fmaf(fk, iq1, q1);
            float q2k = fmaf(fk, iq2, q2);
            float q3k = fmaf(fk, iq3, q3);
            float s1k = fmaf(fk, is1, s1);
            float s2k = fmaf(fk, is2, s2);
            float s3k = fmaf(fk, is3, s3);
            float pwk = fmaf(fk, ipw, pw);

            float w1 = q1k - fminf(fmaxf(q1k, 0.0f), L1);
            float w2 = q2k - fminf(fmaxf(q2k, 0.0f), L2);
            float w3 = q3k - fminf(fmaxf(q3k, 0.0f), L3);
            float d1e = fmaf(w1, w1, s1k * s1k);
            float d2e = fmaf(w2, w2, s2k * s2k);
            float d3e = fmaf(w3, w3, s3k * s3k);
            float d2d = fminf(fminf(d1e, d2e), d3e);
            if ((imask >> k) & 1u) d2d = 0.0f;
            float dist = fmaf(pwk, pwk, d2d);
            md[k] = fminf(md[k], dist);
        }
    }

    #pragma unroll
    for (int k = 0; k < KPT; ++k)
        atomicMin(&g_md2min[pbase + k], __float_as_uint(md[k]));
    if (par) atomicXor(&g_parity[g], par);
}

__global__ void __launch_bounds__(256)
sdf_finalize(float* __restrict__ out)
{
    int p = blockIdx.x * 256 + threadIdx.x;               // [0, 32768)
    float m = __uint_as_float(g_md2min[p]);
    unsigned par = (g_parity[p >> 5] >> (p & 31)) & 1u;
    out[p] = par ? sqrtf(m) : 0.0f;
}

extern "C" void kernel_launch(void* const* d_in, const int* in_sizes, int n_in,
                              void* d_out, int out_size)
{
    const int* faces = nullptr;
    const float* verts = nullptr;
    for (int i = 0; i < n_in; ++i) {
        if (in_sizes[i] == 3 * N_FACES)   faces = (const int*)d_in[i];
        else if (in_sizes[i] == 3 * 1026) verts = (const float*)d_in[i];
    }
    if (!faces) faces = (const int*)d_in[0];
    if (!verts) verts = (const float*)d_in[1];

    sdf_init<<<N_PTS / 4 / 256, 256>>>();
    dim3 grid(N_GROUPS / THREADS, N_CHUNKS);              // 8 x 74 = 592 blocks
    sdf_main<<<grid, THREADS>>>(faces, verts);
    sdf_finalize<<<N_PTS / 256, 256>>>((float*)d_out);
}